// round 14
// baseline (speedup 1.0000x reference)
#include <cuda_runtime.h>
#include <cuda_fp16.h>
#include <math.h>
#include <stdint.h>

// ---------------- problem constants ----------------
#define BB     4
#define PP     65536
#define NPTS   (BB * PP)
#define TD     32
#define HID    128
#define CD     36
#define FIN    68
#define RES    256

#define NP     96               // points per CTA (grid has one partial CTA)
#define NTHR   384              // 12 warps: mt = warp%3 (32 rows), ng = warp/3 (32 cols)
#define STRIDE 136              // padded row stride (elems) for X and W
#define ROWB   (STRIDE * 2)     // 272 B per row
#define WPLANE (128 * ROWB)     // 34816
#define HSTR   88               // H row stride (elems), K 0..79
#define HROWB  (HSTR * 2)       // 176

// smem layout (bytes). H aliases X (H dies at first X write).
#define X_HI      0             // X plane (96*272 = 26112); H aliased (96*176 = 16896)
#define W_A       26112         // weight buffer A (34816)
#define W_B       60928         // weight buffer B (34816)
#define W_OUT     95744         // w_out buffer (2176)
#define SM_BIAS   97920         // 772 floats (3088)
#define SM_COORD  101008        // 288 floats (1152)
#define SMEM_BYTES 102160

// ---------------- device scratch ----------------
__device__ __align__(16) __half g_tp[12 * RES * RES * TD];   // fp16 triplane [plane][hw][32ch]
// slots: 0=w_skip 1=w_in 2=w_b0 3=w_b1 4=w_a0 5=w_a1 (WPLANE each), 6=w_out (8*ROWB)
__device__ __align__(16) unsigned char g_wp[6 * WPLANE + 8 * ROWB];

// ---------------- helpers ----------------
__device__ __forceinline__ uint32_t smem_u32(const void* p) {
    uint32_t a;
    asm("{ .reg .u64 t; cvta.to.shared.u64 t, %1; cvt.u32.u64 %0, t; }" : "=r"(a) : "l"(p));
    return a;
}
__device__ __forceinline__ void ldsm4(uint32_t a, uint32_t r[4]) {
    asm volatile("ldmatrix.sync.aligned.m8n8.x4.shared.b16 {%0,%1,%2,%3}, [%4];"
                 : "=r"(r[0]), "=r"(r[1]), "=r"(r[2]), "=r"(r[3]) : "r"(a));
}
__device__ __forceinline__ void ldsm2(uint32_t a, uint32_t r[2]) {
    asm volatile("ldmatrix.sync.aligned.m8n8.x2.shared.b16 {%0,%1}, [%2];"
                 : "=r"(r[0]), "=r"(r[1]) : "r"(a));
}
__device__ __forceinline__ void mma16816(float d[4], const uint32_t a[4], const uint32_t b[2]) {
    asm volatile("mma.sync.aligned.m16n8k16.row.col.f32.f16.f16.f32 "
                 "{%0,%1,%2,%3}, {%4,%5,%6,%7}, {%8,%9}, {%0,%1,%2,%3};"
                 : "+f"(d[0]), "+f"(d[1]), "+f"(d[2]), "+f"(d[3])
                 : "r"(a[0]), "r"(a[1]), "r"(a[2]), "r"(a[3]), "r"(b[0]), "r"(b[1]));
}

// cp.async
__device__ __forceinline__ void cpa_stage(uint32_t dst, const unsigned char* src, int bytes, int tid) {
    for (int i = tid * 16; i < bytes; i += NTHR * 16)
        asm volatile("cp.async.cg.shared.global [%0], [%1], 16;" :: "r"(dst + i), "l"(src + i) : "memory");
}
#define CPA_COMMIT()  asm volatile("cp.async.commit_group;" ::: "memory")
#define CPA_WAIT0()   asm volatile("cp.async.wait_group 0;" ::: "memory")
#define CPA_WAIT1()   asm volatile("cp.async.wait_group 1;" ::: "memory")

// ---------------- merged prep kernel ----------------
#define TP_BLKS (12 * 512)
#define WP_TOT  (6 * 128 * STRIDE + 8 * STRIDE)
__global__ void prep_all_kernel(const float* __restrict__ tri,
                                const float* __restrict__ w_in,
                                const float* __restrict__ w_skip,
                                const float* __restrict__ w_before,
                                const float* __restrict__ w_after,
                                const float* __restrict__ w_out) {
    __shared__ float t[32 * 129 + 4];
    const int blk = blockIdx.x;
    const int tid = threadIdx.x;
    if (blk < TP_BLKS) {
        const int n   = blk >> 9;
        const int hw0 = (blk & 511) * 128;
        const int c   = tid >> 3;
        const int h8  = tid & 7;
        const float* src = tri + (size_t)(n * 32 + c) * 65536 + hw0;
        #pragma unroll
        for (int i = 0; i < 4; i++) {
            int hw = i * 32 + h8 * 4;
            float4 v = *(const float4*)(src + hw);
            float* tr = t + c * 129 + hw;
            tr[0] = v.x; tr[1] = v.y; tr[2] = v.z; tr[3] = v.w;
        }
        __syncthreads();
        #pragma unroll
        for (int i = 0; i < 2; i++) {
            int e  = tid + 256 * i;
            int hw = e >> 2, c8 = e & 3;
            const float* tc = t + (8 * c8) * 129 + hw;
            __half2 h0 = __floats2half2_rn(tc[0 * 129], tc[1 * 129]);
            __half2 h1 = __floats2half2_rn(tc[2 * 129], tc[3 * 129]);
            __half2 h2 = __floats2half2_rn(tc[4 * 129], tc[5 * 129]);
            __half2 h3 = __floats2half2_rn(tc[6 * 129], tc[7 * 129]);
            uint4 v = make_uint4(*(uint32_t*)&h0, *(uint32_t*)&h1,
                                 *(uint32_t*)&h2, *(uint32_t*)&h3);
            *(uint4*)(g_tp + ((size_t)n * 65536 + hw0 + hw) * 32 + c8 * 8) = v;
        }
        return;
    }
    int idx = (blk - TP_BLKS) * 256 + tid;
    if (idx >= WP_TOT) return;
    const int HN = 6 * 128 * STRIDE;
    int slot, o, k;
    size_t sbase;
    if (idx < HN) {
        slot = idx / (128 * STRIDE);
        int e = idx % (128 * STRIDE);
        o = e / STRIDE; k = e % STRIDE;
        sbase = (size_t)slot * WPLANE;
    } else {
        slot = 6;
        int e = idx - HN;
        o = e / STRIDE; k = e % STRIDE;
        sbase = (size_t)6 * WPLANE;
    }
    float v = 0.0f;
    switch (slot) {
        case 0: if (k < FIN) v = w_skip[o * FIN + k]; break;
        case 1: if (k < FIN) v = w_in[o * FIN + k]; break;
        case 2: if (k < HID) v = w_before[o * HID + k]; break;
        case 3: if (k < HID) v = w_before[HID * HID + o * HID + k]; break;
        case 4: if (k < HID) v = w_after[o * HID + k]; break;
        case 5: if (k < HID) v = w_after[HID * HID + o * HID + k]; break;
        case 6: if (o < 4 && k < HID) v = w_out[o * HID + k]; break;
    }
    *(__half*)(g_wp + sbase + (size_t)(o * STRIDE + k) * 2) = __float2half_rn(v);
}

// ---------------- MMA layer ----------------
// Warp computes 32 M-rows (two 16-row subtiles, A16 bytes apart) x 4 n-tiles (32 neurons).
template <int KS, int A16>
__device__ __forceinline__ void mma_layer(uint32_t aA, uint32_t bB4, float D[8][4]) {
    #pragma unroll
    for (int i = 0; i < 8; i++) { D[i][0] = 0.f; D[i][1] = 0.f; D[i][2] = 0.f; D[i][3] = 0.f; }
    #pragma unroll
    for (int k = 0; k < KS; k++) {
        uint32_t A0[4], A1[4];
        ldsm4(aA + k * 32, A0);
        ldsm4(aA + A16 + k * 32, A1);
        #pragma unroll
        for (int p = 0; p < 2; p++) {
            uint32_t Bh[4];
            ldsm4(bB4 + p * (16 * ROWB) + k * 32, Bh);
            mma16816(D[p * 2],         A0, Bh);
            mma16816(D[p * 2 + 1],     A0, Bh + 2);
            mma16816(D[4 + p * 2],     A1, Bh);
            mma16816(D[4 + p * 2 + 1], A1, Bh + 2);
        }
    }
}

// single n-tile (output layer), 16 rows
template <int KS>
__device__ __forceinline__ void mma_layer1(uint32_t aA, uint32_t bB2, float d[4]) {
    d[0] = d[1] = d[2] = d[3] = 0.f;
    #pragma unroll
    for (int k = 0; k < KS; k++) {
        uint32_t Ah[4], Bh[2];
        ldsm4(aA + k * 32, Ah);
        ldsm2(bB2 + k * 32, Bh);
        mma16816(d, Ah, Bh);
    }
}

// pack skip: u[16] = fp16x2 of relu(D + bs)
__device__ __forceinline__ void pack_skip(const float D[8][4], const float* bs,
                                          int tig, int colb, uint32_t u[16]) {
    #pragma unroll
    for (int idx = 0; idx < 8; idx++) {
        int ntl = idx & 3;
        int c0 = colb + ntl * 8 + 2 * tig;
        float b0 = bs[c0], b1 = bs[c0 + 1];
        float x0 = fmaxf(D[idx][0] + b0, 0.f), x1 = fmaxf(D[idx][1] + b1, 0.f);
        float x2 = fmaxf(D[idx][2] + b0, 0.f), x3 = fmaxf(D[idx][3] + b1, 0.f);
        __half2 h0 = __floats2half2_rn(x0, x1);
        __half2 h1 = __floats2half2_rn(x2, x3);
        u[idx * 2]     = *(uint32_t*)&h0;
        u[idx * 2 + 1] = *(uint32_t*)&h1;
    }
}

// epilogue: bias + relu (+ add pre-relu'd skip u), fp16 pack, store into X.
template <bool SK>
__device__ __forceinline__ void epi(unsigned char* sm, const float D[8][4],
                                    const uint32_t u[16], const float* bd,
                                    int pBase, int tig, int colb) {
    #pragma unroll
    for (int mi = 0; mi < 2; mi++) {
        const int rowA = (pBase + mi * 16) * ROWB;
        const int rowB = rowA + 8 * ROWB;
        #pragma unroll
        for (int ntl = 0; ntl < 4; ntl++) {
            int idx = mi * 4 + ntl;
            int c0 = colb + ntl * 8 + 2 * tig;
            float b0 = bd[c0], b1 = bd[c0 + 1];
            float x0 = fmaxf(D[idx][0] + b0, 0.f), x1 = fmaxf(D[idx][1] + b1, 0.f);
            float x2 = fmaxf(D[idx][2] + b0, 0.f), x3 = fmaxf(D[idx][3] + b1, 0.f);
            if (SK) {
                __half2 s0 = *(__half2*)&u[idx * 2];
                __half2 s1 = *(__half2*)&u[idx * 2 + 1];
                x0 += __low2float(s0);  x1 += __high2float(s0);
                x2 += __low2float(s1);  x3 += __high2float(s1);
            }
            __half2 h0 = __floats2half2_rn(x0, x1);
            __half2 h1 = __floats2half2_rn(x2, x3);
            int off = c0 * 2;
            *(uint32_t*)(sm + X_HI + rowA + off) = *(uint32_t*)&h0;
            *(uint32_t*)(sm + X_HI + rowB + off) = *(uint32_t*)&h1;
        }
    }
}

// ---------------- main decoder kernel ----------------
__global__ void __launch_bounds__(NTHR, 2)
decoder_kernel(const float* __restrict__ coords,
               const float* __restrict__ b_in,
               const float* __restrict__ b_skip,
               const float* __restrict__ b_before,
               const float* __restrict__ b_after,
               const float* __restrict__ b_out,
               float* __restrict__ out) {
    extern __shared__ unsigned char sm[];
    const uint32_t sb = smem_u32(sm);
    const int tid  = threadIdx.x;
    const int lane = tid & 31;
    const int warp = tid >> 5;
    const int mt   = warp % 3;      // m-third (32 rows)
    const int ng   = warp / 3;      // n-group (32 neurons)
    const int base = blockIdx.x * NP;

    float* bS = (float*)(sm + SM_BIAS);
    float* cS = (float*)(sm + SM_COORD);

    // prefetch: g0 = w_skip -> W_A;  g1 = w_in -> W_B + w_out -> W_OUT
    cpa_stage(sb + W_A, g_wp + 0 * WPLANE, WPLANE, tid); CPA_COMMIT();
    cpa_stage(sb + W_B, g_wp + 1 * WPLANE, WPLANE, tid);
    cpa_stage(sb + W_OUT, g_wp + 6 * WPLANE, 8 * ROWB, tid);
    CPA_COMMIT();

    // coords (clamped for partial last CTA) + biases
    {
        const int limit = NPTS * 3 - 1;
        for (int i = tid; i < NP * 3; i += NTHR) {
            int src = base * 3 + i;
            cS[i] = coords[src > limit ? limit : src];
        }
    }
    for (int i = tid; i < 772; i += NTHR) {
        float v;
        if (i < 128)      v = b_in[i];
        else if (i < 256) v = b_skip[i - 128];
        else if (i < 512) v = b_before[i - 256];
        else if (i < 768) v = b_after[i - 512];
        else              v = b_out[i - 768];
        bS[i] = v;
    }
    // zero H pad cols 68..79: 96 rows x 12 cols, 4 threads/row
    {
        int p = tid >> 2, q = tid & 3;
        #pragma unroll
        for (int j = 0; j < 3; j++) {
            int k = FIN + q * 3 + j;
            *(uint16_t*)(sm + X_HI + (p * HSTR + k) * 2) = 0;
        }
    }
    __syncthreads();

    // ---- gather + freq encode -> H (fp16, stride 88): 4 threads/point, 96 pts ----
    {
        const int p = tid >> 2;
        const int q = tid & 3;
        const float c0 = cS[p * 3 + 0];
        const float c1 = cS[p * 3 + 1];
        const float c2 = cS[p * 3 + 2];
        const float nrm[3] = {(c0 + 1.0f) * 0.5f, (c1 + 1.0f) * 0.5f, (c2 + 1.0f) * 0.5f};

        for (int a = q; a < 18; a += 4) {
            int d = a / 6;
            int k = a - 6 * d;
            float freq = 3.14159265358979f * (float)(1 << k);
            float s, c;
            __sincosf(nrm[d] * freq, &s, &c);
            int k1 = d * 12 + k, k2 = d * 12 + 6 + k;
            *(__half*)(sm + X_HI + (p * HSTR + k1) * 2) = __float2half_rn(s);
            *(__half*)(sm + X_HI + (p * HSTR + k2) * 2) = __float2half_rn(c);
        }

        int gp = base + p;
        if (gp >= NPTS) gp = NPTS - 1;
        const int b = gp >> 16;
        const float gpx[3] = {c0, c0, c1};
        const float gpy[3] = {c1, c2, c2};
        float acc[8];
        #pragma unroll
        for (int j = 0; j < 8; j++) acc[j] = 0.0f;

        #pragma unroll
        for (int pl = 0; pl < 3; pl++) {
            float ix = (gpx[pl] + 1.0f) * 127.5f;
            float iy = (gpy[pl] + 1.0f) * 127.5f;
            float x0f = floorf(ix), y0f = floorf(iy);
            float fx = ix - x0f, fy = iy - y0f;
            int x0 = min(max((int)x0f, 0), RES - 2);
            int y0 = min(max((int)y0f, 0), RES - 2);
            float w00 = (1.0f - fx) * (1.0f - fy);
            float w10 = fx * (1.0f - fy);
            float w01 = (1.0f - fx) * fy;
            float w11 = fx * fy;
            const __half* bp = g_tp + ((size_t)(b * 3 + pl) * (RES * RES) + y0 * RES + x0) * TD + q * 8;
            uint4 r00 = *(const uint4*)(bp);
            uint4 r10 = *(const uint4*)(bp + TD);
            uint4 r01 = *(const uint4*)(bp + RES * TD);
            uint4 r11 = *(const uint4*)(bp + RES * TD + TD);
            #pragma unroll
            for (int j = 0; j < 4; j++) {
                float2 f00 = __half22float2(((const __half2*)&r00)[j]);
                float2 f10 = __half22float2(((const __half2*)&r10)[j]);
                float2 f01 = __half22float2(((const __half2*)&r01)[j]);
                float2 f11 = __half22float2(((const __half2*)&r11)[j]);
                acc[2 * j]     += w00 * f00.x + w10 * f10.x + w01 * f01.x + w11 * f11.x;
                acc[2 * j + 1] += w00 * f00.y + w10 * f10.y + w01 * f01.y + w11 * f11.y;
            }
        }
        #pragma unroll
        for (int j = 0; j < 8; j++) {
            int k = CD + q * 8 + j;
            *(__half*)(sm + X_HI + (p * HSTR + k) * 2) = __float2half_rn(acc[j]);
        }
    }

    // per-thread fragment addresses
    const int rowM = mt * 32 + (lane & 15);
    const uint32_t aX = sb + X_HI + (uint32_t)((rowM * STRIDE + (lane >> 4) * 8) * 2);
    const uint32_t aH = sb + X_HI + (uint32_t)((rowM * HSTR + (lane >> 4) * 8) * 2);
    const uint32_t bOff4 = (uint32_t)(ng * 32 * ROWB) +
        (uint32_t)((((lane & 7) + (lane >> 4) * 8) * STRIDE + ((lane >> 3) & 1) * 8) * 2);
    const uint32_t bA4 = sb + W_A + bOff4, bB4 = sb + W_B + bOff4;

    const int g     = lane >> 2;
    const int tig   = lane & 3;
    const int pBase = mt * 32 + g;
    const int colb  = ng * 32;

    float D[8][4];
    uint32_t u[16];

    // ---- SKIP: D = Wskip h (W_A); pack u regs ----
    CPA_WAIT1();                       // g0 (w_skip) done
    __syncthreads();
    mma_layer<5, 16 * HROWB>(aH, bA4, D);
    pack_skip(D, bS + 128, tig, colb, u);
    __syncthreads();                   // all done reading W_A
    cpa_stage(sb + W_A, g_wp + 2 * WPLANE, WPLANE, tid); CPA_COMMIT();   // g2: w_b0 -> W_A
    CPA_WAIT1();                       // g1 (w_in, w_out) done
    __syncthreads();

    // ---- L1: D = Win h (W_B) ----
    mma_layer<5, 16 * HROWB>(aH, bB4, D);
    __syncthreads();                   // H dead, W_B free
    cpa_stage(sb + W_B, g_wp + 3 * WPLANE, WPLANE, tid); CPA_COMMIT();   // g3: w_b1 -> W_B
    epi<false>(sm, D, u, bS + 0, pBase, tig, colb);                      // x1 -> X
    CPA_WAIT1();                       // g2 (w_b0) done
    __syncthreads();

    // ---- L2: D = W0 x1 (W_A) ----
    mma_layer<8, 16 * ROWB>(aX, bA4, D);
    __syncthreads();
    cpa_stage(sb + W_A, g_wp + 4 * WPLANE, WPLANE, tid); CPA_COMMIT();   // g4: w_a0 -> W_A
    epi<false>(sm, D, u, bS + 256, pBase, tig, colb);                    // x2 -> X
    CPA_WAIT1();                       // g3 (w_b1) done
    __syncthreads();

    // ---- L3: D = W1 x2 (W_B); x4 = relu(D+b) + u ----
    mma_layer<8, 16 * ROWB>(aX, bB4, D);
    __syncthreads();
    cpa_stage(sb + W_B, g_wp + 5 * WPLANE, WPLANE, tid); CPA_COMMIT();   // g5: w_a1 -> W_B
    epi<true>(sm, D, u, bS + 384, pBase, tig, colb);                     // x4 -> X
    CPA_WAIT1();                       // g4 (w_a0) done
    __syncthreads();

    // ---- L4: D = W2 x4 (W_A) ----
    mma_layer<8, 16 * ROWB>(aX, bA4, D);
    __syncthreads();
    epi<false>(sm, D, u, bS + 512, pBase, tig, colb);                    // x5 -> X
    CPA_WAIT0();                       // g5 (w_a1) done
    __syncthreads();

    // ---- L5: D = W3 x5 (W_B) ----
    mma_layer<8, 16 * ROWB>(aX, bB4, D);
    __syncthreads();
    epi<false>(sm, D, u, bS + 640, pBase, tig, colb);                    // x6 -> X
    __syncthreads();

    // ---- L6: out = Wout x6 (warps 0..5, rows warp*16..+15; cols 0..3 valid) ----
    if (warp < 6) {
        const uint32_t aX6 = sb + X_HI +
            (uint32_t)(((warp * 16 + (lane & 15)) * STRIDE + (lane >> 4) * 8) * 2);
        const uint32_t bO2 = sb + W_OUT +
            (uint32_t)(((lane & 7) * STRIDE + ((lane >> 3) & 1) * 8) * 2);
        float Do[4];
        mma_layer1<8>(aX6, bO2, Do);
        const int pA  = warp * 16 + g;
        const int pB  = pA + 8;
        const int gpA = base + pA, gpB = base + pB;
        const bool okA = gpA < NPTS, okB = gpB < NPTS;
        if (tig == 0) {
            float v0 = Do[0] + bS[768], v1 = Do[1] + bS[769];
            float v2 = Do[2] + bS[768], v3 = Do[3] + bS[769];
            if (okA) {
                out[gpA * 3 + 0] = 1.0f / (1.0f + expf(-v0));
                out[gpA * 3 + 1] = 1.0f / (1.0f + expf(-v1));
            }
            if (okB) {
                out[gpB * 3 + 0] = 1.0f / (1.0f + expf(-v2));
                out[gpB * 3 + 1] = 1.0f / (1.0f + expf(-v3));
            }
        } else if (tig == 1) {
            float v0 = Do[0] + bS[770], v1 = Do[1] + bS[771];
            float v2 = Do[2] + bS[770], v3 = Do[3] + bS[771];
            if (okA) {
                out[gpA * 3 + 2] = 1.0f / (1.0f + expf(-v0));
                float a0 = cS[pA * 3 + 0], a1 = cS[pA * 3 + 1], a2 = cS[pA * 3 + 2];
                bool selA = (a0 > -1.0f) && (a0 < 1.0f) && (a1 > -1.0f) && (a1 < 1.0f) &&
                            (a2 > -1.0f) && (a2 < 1.0f);
                out[3 * NPTS + gpA] = selA ? expf(v1 - 1.0f) : 0.0f;
            }
            if (okB) {
                out[gpB * 3 + 2] = 1.0f / (1.0f + expf(-v2));
                float b0 = cS[pB * 3 + 0], b1 = cS[pB * 3 + 1], b2 = cS[pB * 3 + 2];
                bool selB = (b0 > -1.0f) && (b0 < 1.0f) && (b1 > -1.0f) && (b1 < 1.0f) &&
                            (b2 > -1.0f) && (b2 < 1.0f);
                out[3 * NPTS + gpB] = selB ? expf(v3 - 1.0f) : 0.0f;
            }
        }
    }
}

// ---------------- launch ----------------
extern "C" void kernel_launch(void* const* d_in, const int* in_sizes, int n_in,
                              void* d_out, int out_size) {
    const float* triplane = (const float*)d_in[0];
    const float* coords   = (const float*)d_in[1];
    const float* w_in     = (const float*)d_in[2];
    const float* b_in     = (const float*)d_in[3];
    const float* w_skip   = (const float*)d_in[4];
    const float* b_skip   = (const float*)d_in[5];
    const float* w_before = (const float*)d_in[6];
    const float* b_before = (const float*)d_in[7];
    const float* w_after  = (const float*)d_in[8];
    const float* b_after  = (const float*)d_in[9];
    const float* w_out    = (const float*)d_in[10];
    const float* b_out    = (const float*)d_in[11];
    float* out = (float*)d_out;

    static bool attr_set = false;
    if (!attr_set) {
        cudaFuncSetAttribute(decoder_kernel,
                             cudaFuncAttributeMaxDynamicSharedMemorySize, SMEM_BYTES);
        attr_set = true;
    }

    const int wp_blks = (WP_TOT + 255) / 256;
    prep_all_kernel<<<TP_BLKS + wp_blks, 256>>>(
        triplane, w_in, w_skip, w_before, w_after, w_out);
    decoder_kernel<<<(NPTS + NP - 1) / NP, NTHR, SMEM_BYTES>>>(
        coords, b_in, b_skip, b_before, b_after, b_out, out);
}

// round 16
// speedup vs baseline: 1.0341x; 1.0341x over previous
#include <cuda_runtime.h>
#include <cuda_fp16.h>
#include <math.h>
#include <stdint.h>

// ---------------- problem constants ----------------
#define BB     4
#define PP     65536
#define NPTS   (BB * PP)
#define TD     32
#define HID    128
#define CD     36
#define FIN    68
#define RES    256

#define NP     64               // points per CTA
#define NTHR   256              // 8 warps: warp&1 = m-half (32 rows), warp>>1 = n-group (32 cols)
#define STRIDE 136              // padded row stride (elems) for X and W
#define ROWB   (STRIDE * 2)     // 272 B per row
#define WPLANE (128 * ROWB)     // 34816
#define HSTR   88               // H row stride (elems), K 0..79
#define HROWB  (HSTR * 2)       // 176

// smem layout (bytes). H aliases X (H dies at first X write).
#define X_HI      0             // X plane (17408); H aliased (11264)
#define W_0       17408         // single W buffer (34816)
#define W_OUT     52224         // w_out buffer (2176)
#define SM_BIAS   54400         // 772 floats
#define SM_COORD  57488         // 192 floats
#define SMEM_BYTES 58256

// ---------------- device scratch ----------------
__device__ __align__(16) __half g_tp[12 * RES * RES * TD];   // fp16 triplane [plane][hw][32ch]
// slots: 0=w_skip 1=w_in 2=w_b0 3=w_b1 4=w_a0 5=w_a1 (WPLANE each), 6=w_out (8*ROWB)
__device__ __align__(16) unsigned char g_wp[6 * WPLANE + 8 * ROWB];

// ---------------- helpers ----------------
__device__ __forceinline__ uint32_t smem_u32(const void* p) {
    uint32_t a;
    asm("{ .reg .u64 t; cvta.to.shared.u64 t, %1; cvt.u32.u64 %0, t; }" : "=r"(a) : "l"(p));
    return a;
}
__device__ __forceinline__ void ldsm4(uint32_t a, uint32_t r[4]) {
    asm volatile("ldmatrix.sync.aligned.m8n8.x4.shared.b16 {%0,%1,%2,%3}, [%4];"
                 : "=r"(r[0]), "=r"(r[1]), "=r"(r[2]), "=r"(r[3]) : "r"(a));
}
__device__ __forceinline__ void ldsm2(uint32_t a, uint32_t r[2]) {
    asm volatile("ldmatrix.sync.aligned.m8n8.x2.shared.b16 {%0,%1}, [%2];"
                 : "=r"(r[0]), "=r"(r[1]) : "r"(a));
}
__device__ __forceinline__ void mma16816(float d[4], const uint32_t a[4], const uint32_t b[2]) {
    asm volatile("mma.sync.aligned.m16n8k16.row.col.f32.f16.f16.f32 "
                 "{%0,%1,%2,%3}, {%4,%5,%6,%7}, {%8,%9}, {%0,%1,%2,%3};"
                 : "+f"(d[0]), "+f"(d[1]), "+f"(d[2]), "+f"(d[3])
                 : "r"(a[0]), "r"(a[1]), "r"(a[2]), "r"(a[3]), "r"(b[0]), "r"(b[1]));
}

// cp.async
__device__ __forceinline__ void cpa_stage(uint32_t dst, const unsigned char* src, int bytes, int tid) {
    for (int i = tid * 16; i < bytes; i += NTHR * 16)
        asm volatile("cp.async.cg.shared.global [%0], [%1], 16;" :: "r"(dst + i), "l"(src + i) : "memory");
}
#define CPA_COMMIT()  asm volatile("cp.async.commit_group;" ::: "memory")
#define CPA_WAIT0()   asm volatile("cp.async.wait_group 0;" ::: "memory")

// ---------------- merged prep kernel ----------------
#define TP_BLKS (12 * 512)
#define WP_TOT  (6 * 128 * STRIDE + 8 * STRIDE)
__global__ void prep_all_kernel(const float* __restrict__ tri,
                                const float* __restrict__ w_in,
                                const float* __restrict__ w_skip,
                                const float* __restrict__ w_before,
                                const float* __restrict__ w_after,
                                const float* __restrict__ w_out) {
    __shared__ float t[32 * 129 + 4];
    const int blk = blockIdx.x;
    const int tid = threadIdx.x;
    if (blk < TP_BLKS) {
        const int n   = blk >> 9;
        const int hw0 = (blk & 511) * 128;
        const int c   = tid >> 3;
        const int h8  = tid & 7;
        const float* src = tri + (size_t)(n * 32 + c) * 65536 + hw0;
        #pragma unroll
        for (int i = 0; i < 4; i++) {
            int hw = i * 32 + h8 * 4;
            float4 v = *(const float4*)(src + hw);
            float* tr = t + c * 129 + hw;
            tr[0] = v.x; tr[1] = v.y; tr[2] = v.z; tr[3] = v.w;
        }
        __syncthreads();
        #pragma unroll
        for (int i = 0; i < 2; i++) {
            int e  = tid + 256 * i;
            int hw = e >> 2, c8 = e & 3;
            const float* tc = t + (8 * c8) * 129 + hw;
            __half2 h0 = __floats2half2_rn(tc[0 * 129], tc[1 * 129]);
            __half2 h1 = __floats2half2_rn(tc[2 * 129], tc[3 * 129]);
            __half2 h2 = __floats2half2_rn(tc[4 * 129], tc[5 * 129]);
            __half2 h3 = __floats2half2_rn(tc[6 * 129], tc[7 * 129]);
            uint4 v = make_uint4(*(uint32_t*)&h0, *(uint32_t*)&h1,
                                 *(uint32_t*)&h2, *(uint32_t*)&h3);
            *(uint4*)(g_tp + ((size_t)n * 65536 + hw0 + hw) * 32 + c8 * 8) = v;
        }
        return;
    }
    int idx = (blk - TP_BLKS) * 256 + tid;
    if (idx >= WP_TOT) return;
    const int HN = 6 * 128 * STRIDE;
    int slot, o, k;
    size_t sbase;
    if (idx < HN) {
        slot = idx / (128 * STRIDE);
        int e = idx % (128 * STRIDE);
        o = e / STRIDE; k = e % STRIDE;
        sbase = (size_t)slot * WPLANE;
    } else {
        slot = 6;
        int e = idx - HN;
        o = e / STRIDE; k = e % STRIDE;
        sbase = (size_t)6 * WPLANE;
    }
    float v = 0.0f;
    switch (slot) {
        case 0: if (k < FIN) v = w_skip[o * FIN + k]; break;
        case 1: if (k < FIN) v = w_in[o * FIN + k]; break;
        case 2: if (k < HID) v = w_before[o * HID + k]; break;
        case 3: if (k < HID) v = w_before[HID * HID + o * HID + k]; break;
        case 4: if (k < HID) v = w_after[o * HID + k]; break;
        case 5: if (k < HID) v = w_after[HID * HID + o * HID + k]; break;
        case 6: if (o < 4 && k < HID) v = w_out[o * HID + k]; break;
    }
    *(__half*)(g_wp + sbase + (size_t)(o * STRIDE + k) * 2) = __float2half_rn(v);
}

// ---------------- MMA layer ----------------
// Warp computes 32 M-rows (two 16-row subtiles, A16 bytes apart) x 4 n-tiles (32 neurons).
template <int KS, int A16>
__device__ __forceinline__ void mma_layer(uint32_t aA, uint32_t bB4, float D[8][4]) {
    #pragma unroll
    for (int i = 0; i < 8; i++) { D[i][0] = 0.f; D[i][1] = 0.f; D[i][2] = 0.f; D[i][3] = 0.f; }
    #pragma unroll
    for (int k = 0; k < KS; k++) {
        uint32_t A0[4], A1[4];
        ldsm4(aA + k * 32, A0);
        ldsm4(aA + A16 + k * 32, A1);
        #pragma unroll
        for (int p = 0; p < 2; p++) {
            uint32_t Bh[4];
            ldsm4(bB4 + p * (16 * ROWB) + k * 32, Bh);
            mma16816(D[p * 2],         A0, Bh);
            mma16816(D[p * 2 + 1],     A0, Bh + 2);
            mma16816(D[4 + p * 2],     A1, Bh);
            mma16816(D[4 + p * 2 + 1], A1, Bh + 2);
        }
    }
}

// single n-tile (output layer), 16 rows
template <int KS>
__device__ __forceinline__ void mma_layer1(uint32_t aA, uint32_t bB2, float d[4]) {
    d[0] = d[1] = d[2] = d[3] = 0.f;
    #pragma unroll
    for (int k = 0; k < KS; k++) {
        uint32_t Ah[4], Bh[2];
        ldsm4(aA + k * 32, Ah);
        ldsm2(bB2 + k * 32, Bh);
        mma16816(d, Ah, Bh);
    }
}

// pack skip: u[16] = fp16x2 of relu(D + bs)
__device__ __forceinline__ void pack_skip(const float D[8][4], const float* bs,
                                          int tig, int colb, uint32_t u[16]) {
    #pragma unroll
    for (int idx = 0; idx < 8; idx++) {
        int ntl = idx & 3;
        int c0 = colb + ntl * 8 + 2 * tig;
        float b0 = bs[c0], b1 = bs[c0 + 1];
        float x0 = fmaxf(D[idx][0] + b0, 0.f), x1 = fmaxf(D[idx][1] + b1, 0.f);
        float x2 = fmaxf(D[idx][2] + b0, 0.f), x3 = fmaxf(D[idx][3] + b1, 0.f);
        __half2 h0 = __floats2half2_rn(x0, x1);
        __half2 h1 = __floats2half2_rn(x2, x3);
        u[idx * 2]     = *(uint32_t*)&h0;
        u[idx * 2 + 1] = *(uint32_t*)&h1;
    }
}

// epilogue: bias + relu (+ add pre-relu'd skip u), fp16 pack, store into X.
template <bool SK>
__device__ __forceinline__ void epi(unsigned char* sm, const float D[8][4],
                                    const uint32_t u[16], const float* bd,
                                    int pBase, int tig, int colb) {
    #pragma unroll
    for (int mi = 0; mi < 2; mi++) {
        const int rowA = (pBase + mi * 16) * ROWB;
        const int rowB = rowA + 8 * ROWB;
        #pragma unroll
        for (int ntl = 0; ntl < 4; ntl++) {
            int idx = mi * 4 + ntl;
            int c0 = colb + ntl * 8 + 2 * tig;
            float b0 = bd[c0], b1 = bd[c0 + 1];
            float x0 = fmaxf(D[idx][0] + b0, 0.f), x1 = fmaxf(D[idx][1] + b1, 0.f);
            float x2 = fmaxf(D[idx][2] + b0, 0.f), x3 = fmaxf(D[idx][3] + b1, 0.f);
            if (SK) {
                __half2 s0 = *(__half2*)&u[idx * 2];
                __half2 s1 = *(__half2*)&u[idx * 2 + 1];
                x0 += __low2float(s0);  x1 += __high2float(s0);
                x2 += __low2float(s1);  x3 += __high2float(s1);
            }
            __half2 h0 = __floats2half2_rn(x0, x1);
            __half2 h1 = __floats2half2_rn(x2, x3);
            int off = c0 * 2;
            *(uint32_t*)(sm + X_HI + rowA + off) = *(uint32_t*)&h0;
            *(uint32_t*)(sm + X_HI + rowB + off) = *(uint32_t*)&h1;
        }
    }
}

// ---------------- main decoder kernel ----------------
__global__ void __launch_bounds__(NTHR, 3)
decoder_kernel(const float* __restrict__ coords,
               const float* __restrict__ b_in,
               const float* __restrict__ b_skip,
               const float* __restrict__ b_before,
               const float* __restrict__ b_after,
               const float* __restrict__ b_out,
               float* __restrict__ out) {
    extern __shared__ unsigned char sm[];
    const uint32_t sb = smem_u32(sm);
    const int tid  = threadIdx.x;
    const int lane = tid & 31;
    const int warp = tid >> 5;
    const int mt   = warp & 1;      // m-half (32 rows)
    const int ng   = warp >> 1;     // n-group (32 neurons)
    const int base = blockIdx.x * NP;

    float* bS = (float*)(sm + SM_BIAS);
    float* cS = (float*)(sm + SM_COORD);

    // stage w_skip + w_out immediately (overlaps with gather)
    cpa_stage(sb + W_0, g_wp + 0 * WPLANE, WPLANE, tid);
    cpa_stage(sb + W_OUT, g_wp + 6 * WPLANE, 8 * ROWB, tid);
    CPA_COMMIT();

    // coords + biases
    for (int i = tid; i < NP * 3; i += NTHR) cS[i] = coords[base * 3 + i];
    for (int i = tid; i < 772; i += NTHR) {
        float v;
        if (i < 128)      v = b_in[i];
        else if (i < 256) v = b_skip[i - 128];
        else if (i < 512) v = b_before[i - 256];
        else if (i < 768) v = b_after[i - 512];
        else              v = b_out[i - 768];
        bS[i] = v;
    }
    // zero H pad cols 68..79: 64 rows x 12 cols, 4 threads/row
    {
        int p = tid >> 2, q = tid & 3;
        #pragma unroll
        for (int j = 0; j < 3; j++) {
            int k = FIN + q * 3 + j;
            *(uint16_t*)(sm + X_HI + (p * HSTR + k) * 2) = 0;
        }
    }
    __syncthreads();

    // ---- gather + freq encode -> H (fp16, stride 88): 4 threads/point ----
    {
        const int p = tid >> 2;
        const int q = tid & 3;
        const float c0 = cS[p * 3 + 0];
        const float c1 = cS[p * 3 + 1];
        const float c2 = cS[p * 3 + 2];
        const float nrm[3] = {(c0 + 1.0f) * 0.5f, (c1 + 1.0f) * 0.5f, (c2 + 1.0f) * 0.5f};

        for (int a = q; a < 18; a += 4) {
            int d = a / 6;
            int k = a - 6 * d;
            float freq = 3.14159265358979f * (float)(1 << k);
            float s, c;
            __sincosf(nrm[d] * freq, &s, &c);
            int k1 = d * 12 + k, k2 = d * 12 + 6 + k;
            *(__half*)(sm + X_HI + (p * HSTR + k1) * 2) = __float2half_rn(s);
            *(__half*)(sm + X_HI + (p * HSTR + k2) * 2) = __float2half_rn(c);
        }

        const int b = (base + p) >> 16;
        const float gpx[3] = {c0, c0, c1};
        const float gpy[3] = {c1, c2, c2};
        float acc[8];
        #pragma unroll
        for (int j = 0; j < 8; j++) acc[j] = 0.0f;

        #pragma unroll
        for (int pl = 0; pl < 3; pl++) {
            float ix = (gpx[pl] + 1.0f) * 127.5f;
            float iy = (gpy[pl] + 1.0f) * 127.5f;
            float x0f = floorf(ix), y0f = floorf(iy);
            float fx = ix - x0f, fy = iy - y0f;
            int x0 = min(max((int)x0f, 0), RES - 2);
            int y0 = min(max((int)y0f, 0), RES - 2);
            float w00 = (1.0f - fx) * (1.0f - fy);
            float w10 = fx * (1.0f - fy);
            float w01 = (1.0f - fx) * fy;
            float w11 = fx * fy;
            const __half* bp = g_tp + ((size_t)(b * 3 + pl) * (RES * RES) + y0 * RES + x0) * TD + q * 8;
            uint4 r00 = *(const uint4*)(bp);
            uint4 r10 = *(const uint4*)(bp + TD);
            uint4 r01 = *(const uint4*)(bp + RES * TD);
            uint4 r11 = *(const uint4*)(bp + RES * TD + TD);
            #pragma unroll
            for (int j = 0; j < 4; j++) {
                float2 f00 = __half22float2(((const __half2*)&r00)[j]);
                float2 f10 = __half22float2(((const __half2*)&r10)[j]);
                float2 f01 = __half22float2(((const __half2*)&r01)[j]);
                float2 f11 = __half22float2(((const __half2*)&r11)[j]);
                acc[2 * j]     += w00 * f00.x + w10 * f10.x + w01 * f01.x + w11 * f11.x;
                acc[2 * j + 1] += w00 * f00.y + w10 * f10.y + w01 * f01.y + w11 * f11.y;
            }
        }
        // packed stores: base offset = p*176 + 72 + q*16, 8-byte aligned -> two uint2 stores
        {
            __half2 h0 = __floats2half2_rn(acc[0], acc[1]);
            __half2 h1 = __floats2half2_rn(acc[2], acc[3]);
            __half2 h2 = __floats2half2_rn(acc[4], acc[5]);
            __half2 h3 = __floats2half2_rn(acc[6], acc[7]);
            unsigned char* dst = sm + X_HI + (p * HSTR + CD + q * 8) * 2;
            *(uint2*)(dst)     = make_uint2(*(uint32_t*)&h0, *(uint32_t*)&h1);
            *(uint2*)(dst + 8) = make_uint2(*(uint32_t*)&h2, *(uint32_t*)&h3);
        }
    }

    // per-thread fragment addresses
    const int rowM = mt * 32 + (lane & 15);
    const uint32_t aX = sb + X_HI + (uint32_t)((rowM * STRIDE + (lane >> 4) * 8) * 2);
    const uint32_t aH = sb + X_HI + (uint32_t)((rowM * HSTR + (lane >> 4) * 8) * 2);
    const uint32_t bW4 = sb + W_0 + (uint32_t)(ng * 32 * ROWB) +
        (uint32_t)((((lane & 7) + (lane >> 4) * 8) * STRIDE + ((lane >> 3) & 1) * 8) * 2);

    const int g     = lane >> 2;
    const int tig   = lane & 3;
    const int pBase = mt * 32 + g;
    const int colb  = ng * 32;

    float D[8][4];
    uint32_t u[16];

    // ---- SKIP: D = Wskip h (W_0); pack u regs ----
    CPA_WAIT0();
    __syncthreads();
    mma_layer<5, 16 * HROWB>(aH, bW4, D);
    pack_skip(D, bS + 128, tig, colb, u);
    __syncthreads();                   // all done reading W_0
    cpa_stage(sb + W_0, g_wp + 1 * WPLANE, WPLANE, tid); CPA_COMMIT();   // w_in
    CPA_WAIT0();
    __syncthreads();

    // ---- L1: D = Win h ----
    mma_layer<5, 16 * HROWB>(aH, bW4, D);
    __syncthreads();                   // H dead, W_0 free
    cpa_stage(sb + W_0, g_wp + 2 * WPLANE, WPLANE, tid); CPA_COMMIT();   // w_b0
    epi<false>(sm, D, u, bS + 0, pBase, tig, colb);                      // x1 -> X
    CPA_WAIT0();
    __syncthreads();

    // ---- L2: D = W0 x1 ----
    mma_layer<8, 16 * ROWB>(aX, bW4, D);
    __syncthreads();
    cpa_stage(sb + W_0, g_wp + 3 * WPLANE, WPLANE, tid); CPA_COMMIT();   // w_b1
    epi<false>(sm, D, u, bS + 256, pBase, tig, colb);                    // x2 -> X
    CPA_WAIT0();
    __syncthreads();

    // ---- L3: D = W1 x2 ; x4 = relu(D+b) + u ----
    mma_layer<8, 16 * ROWB>(aX, bW4, D);
    __syncthreads();
    cpa_stage(sb + W_0, g_wp + 4 * WPLANE, WPLANE, tid); CPA_COMMIT();   // w_a0
    epi<true>(sm, D, u, bS + 384, pBase, tig, colb);                     // x4 -> X
    CPA_WAIT0();
    __syncthreads();

    // ---- L4: D = W2 x4 ----
    mma_layer<8, 16 * ROWB>(aX, bW4, D);
    __syncthreads();
    cpa_stage(sb + W_0, g_wp + 5 * WPLANE, WPLANE, tid); CPA_COMMIT();   // w_a1
    epi<false>(sm, D, u, bS + 512, pBase, tig, colb);                    // x5 -> X
    CPA_WAIT0();
    __syncthreads();

    // ---- L5: D = W3 x5 ----
    mma_layer<8, 16 * ROWB>(aX, bW4, D);
    __syncthreads();
    epi<false>(sm, D, u, bS + 640, pBase, tig, colb);                    // x6 -> X
    __syncthreads();

    // ---- L6: out = Wout x6 (warps 0..3, rows warp*16..+15; cols 0..3 valid) ----
    if (warp < 4) {
        const uint32_t aX6 = sb + X_HI +
            (uint32_t)(((warp * 16 + (lane & 15)) * STRIDE + (lane >> 4) * 8) * 2);
        const uint32_t bO2 = sb + W_OUT +
            (uint32_t)(((lane & 7) * STRIDE + ((lane >> 3) & 1) * 8) * 2);
        float Do[4];
        mma_layer1<8>(aX6, bO2, Do);
        const int pA  = warp * 16 + g;
        const int pB  = pA + 8;
        const int gpA = base + pA, gpB = base + pB;
        if (tig == 0) {
            float v0 = Do[0] + bS[768], v1 = Do[1] + bS[769];
            float v2 = Do[2] + bS[768], v3 = Do[3] + bS[769];
            out[gpA * 3 + 0] = 1.0f / (1.0f + __expf(-v0));
            out[gpA * 3 + 1] = 1.0f / (1.0f + __expf(-v1));
            out[gpB * 3 + 0] = 1.0f / (1.0f + __expf(-v2));
            out[gpB * 3 + 1] = 1.0f / (1.0f + __expf(-v3));
        } else if (tig == 1) {
            float v0 = Do[0] + bS[770], v1 = Do[1] + bS[771];
            float v2 = Do[2] + bS[770], v3 = Do[3] + bS[771];
            out[gpA * 3 + 2] = 1.0f / (1.0f + __expf(-v0));
            out[gpB * 3 + 2] = 1.0f / (1.0f + __expf(-v2));
            float a0 = cS[pA * 3 + 0], a1 = cS[pA * 3 + 1], a2 = cS[pA * 3 + 2];
            bool selA = (a0 > -1.0f) && (a0 < 1.0f) && (a1 > -1.0f) && (a1 < 1.0f) &&
                        (a2 > -1.0f) && (a2 < 1.0f);
            float b0 = cS[pB * 3 + 0], b1 = cS[pB * 3 + 1], b2 = cS[pB * 3 + 2];
            bool selB = (b0 > -1.0f) && (b0 < 1.0f) && (b1 > -1.0f) && (b1 < 1.0f) &&
                        (b2 > -1.0f) && (b2 < 1.0f);
            out[3 * NPTS + gpA] = selA ? __expf(v1 - 1.0f) : 0.0f;
            out[3 * NPTS + gpB] = selB ? __expf(v3 - 1.0f) : 0.0f;
        }
    }
}

// ---------------- launch ----------------
extern "C" void kernel_launch(void* const* d_in, const int* in_sizes, int n_in,
                              void* d_out, int out_size) {
    const float* triplane = (const float*)d_in[0];
    const float* coords   = (const float*)d_in[1];
    const float* w_in     = (const float*)d_in[2];
    const float* b_in     = (const float*)d_in[3];
    const float* w_skip   = (const float*)d_in[4];
    const float* b_skip   = (const float*)d_in[5];
    const float* w_before = (const float*)d_in[6];
    const float* b_before = (const float*)d_in[7];
    const float* w_after  = (const float*)d_in[8];
    const float* b_after  = (const float*)d_in[9];
    const float* w_out    = (const float*)d_in[10];
    const float* b_out    = (const float*)d_in[11];
    float* out = (float*)d_out;

    static bool attr_set = false;
    if (!attr_set) {
        cudaFuncSetAttribute(decoder_kernel,
                             cudaFuncAttributeMaxDynamicSharedMemorySize, SMEM_BYTES);
        attr_set = true;
    }

    const int wp_blks = (WP_TOT + 255) / 256;
    prep_all_kernel<<<TP_BLKS + wp_blks, 256>>>(
        triplane, w_in, w_skip, w_before, w_after, w_out);
    decoder_kernel<<<NPTS / NP, NTHR, SMEM_BYTES>>>(
        coords, b_in, b_skip, b_before, b_after, b_out, out);
}